// round 6
// baseline (speedup 1.0000x reference)
#include <cuda_runtime.h>
#include <cuda_bf16.h>
#include <cstdint>

// Shapes: x (4,2048,2048) -> M=8192, K=2048; weight (8192,2048) -> N=8192.
#define M_TOK 8192
#define K_DIM 2048
#define N_OUT 8192
#define W_ELEMS (N_OUT * K_DIM)
#define X_ELEMS (M_TOK * K_DIM)

// GEMM tiling (bf16: BK=64 elems = 128 bytes per SMEM row)
#define BM 128
#define BN 256
#define BK 64
#define CHUNKS (K_DIM / BK)          // 32
#define STAGES 4
#define A_BYTES (BM * 128)           // 16384
#define B_BYTES (BN * 128)           // 32768
#define STAGE_BYTES (A_BYTES + B_BYTES)
#define SMEM_TOTAL (1024 + STAGES * STAGE_BYTES)   // 197632

// ---- device scratch ----
__device__ float g_gamma;
__device__ float g_partial[2048];
__device__ float g_scale[M_TOK];
__device__ __nv_bfloat16 g_xb[X_ELEMS];
__device__ __nv_bfloat16 g_wb[W_ELEMS];

// ======================= helpers =======================
__device__ __forceinline__ uint32_t smem_u32(const void* p) {
    uint32_t a;
    asm("{ .reg .u64 t; cvta.to.shared.u64 t, %1; cvt.u32.u64 %0, t; }" : "=r"(a) : "l"(p));
    return a;
}
#define SW128(o) ((o) ^ (((o) >> 3) & 0x70))

__device__ __forceinline__ void cp16(uint32_t dst, const void* src) {
    asm volatile("cp.async.cg.shared.global [%0], [%1], 16;" :: "r"(dst), "l"(src));
}
#define CP_COMMIT() asm volatile("cp.async.commit_group;" ::: "memory")
#define CP_WAIT(n)  asm volatile("cp.async.wait_group %0;" :: "n"(n) : "memory")

#define LDSM4(r, a)                                                                  \
    asm volatile("ldmatrix.sync.aligned.m8n8.x4.shared.b16 {%0,%1,%2,%3}, [%4];"     \
        : "=r"((r)[0]), "=r"((r)[1]), "=r"((r)[2]), "=r"((r)[3]) : "r"(a))

#define MMAB(d, a, b0, b1)                                                           \
    asm volatile("mma.sync.aligned.m16n8k16.row.col.f32.bf16.bf16.f32 "              \
        "{%0,%1,%2,%3}, {%4,%5,%6,%7}, {%8,%9}, {%0,%1,%2,%3};"                      \
        : "+f"((d)[0]), "+f"((d)[1]), "+f"((d)[2]), "+f"((d)[3])                     \
        : "r"((a)[0]), "r"((a)[1]), "r"((a)[2]), "r"((a)[3]), "r"(b0), "r"(b1))

// ======================= prepasses =======================
__global__ void absw_partial(const float* __restrict__ w) {
    float s = 0.f;
    const float4* w4 = (const float4*)w;
    int stride = gridDim.x * blockDim.x;
    for (int i = blockIdx.x * blockDim.x + threadIdx.x; i < W_ELEMS / 4; i += stride) {
        float4 v = w4[i];
        s += fabsf(v.x) + fabsf(v.y) + fabsf(v.z) + fabsf(v.w);
    }
    __shared__ float sh[8];
    #pragma unroll
    for (int o = 16; o; o >>= 1) s += __shfl_down_sync(0xFFFFFFFFu, s, o);
    if ((threadIdx.x & 31) == 0) sh[threadIdx.x >> 5] = s;
    __syncthreads();
    if (threadIdx.x == 0) {
        float t = 0.f;
        #pragma unroll
        for (int i = 0; i < 8; ++i) t += sh[i];
        g_partial[blockIdx.x] = t;
    }
}

__global__ void absw_final() {
    float s = 0.f;
    for (int i = threadIdx.x; i < 2048; i += 1024) s += g_partial[i];
    __shared__ float sh[32];
    #pragma unroll
    for (int o = 16; o; o >>= 1) s += __shfl_down_sync(0xFFFFFFFFu, s, o);
    if ((threadIdx.x & 31) == 0) sh[threadIdx.x >> 5] = s;
    __syncthreads();
    if (threadIdx.x == 0) {
        float t = 0.f;
        #pragma unroll
        for (int i = 0; i < 32; ++i) t += sh[i];
        g_gamma = fmaxf(t / (float)W_ELEMS, 1e-5f);
    }
}

__global__ void quant_w(const float* __restrict__ w) {
    float inv_g = 1.0f / g_gamma;
    const float4* w4 = (const float4*)w;
    uint2* out = (uint2*)g_wb;
    int stride = gridDim.x * blockDim.x;
    for (int i = blockIdx.x * blockDim.x + threadIdx.x; i < W_ELEMS / 4; i += stride) {
        float4 v = w4[i];
        float b0 = rintf(fminf(fmaxf(v.x * inv_g, -1.f), 1.f));
        float b1 = rintf(fminf(fmaxf(v.y * inv_g, -1.f), 1.f));
        float b2 = rintf(fminf(fmaxf(v.z * inv_g, -1.f), 1.f));
        float b3 = rintf(fminf(fmaxf(v.w * inv_g, -1.f), 1.f));
        __nv_bfloat162 p0 = __floats2bfloat162_rn(b0, b1);
        __nv_bfloat162 p1 = __floats2bfloat162_rn(b2, b3);
        out[i] = make_uint2(*(uint32_t*)&p0, *(uint32_t*)&p1);
    }
}

__global__ void ln_quant_x(const float* __restrict__ x) {
    int row = blockIdx.x;
    const float4* xr = (const float4*)(x + (size_t)row * K_DIM);
    int tid = threadIdx.x;

    float4 p0 = xr[tid];
    float4 p1 = xr[tid + 256];
    float v[8] = {p0.x, p0.y, p0.z, p0.w, p1.x, p1.y, p1.z, p1.w};

    float s = 0.f, ss = 0.f;
    #pragma unroll
    for (int i = 0; i < 8; ++i) { s += v[i]; ss += v[i] * v[i]; }

    __shared__ float sh_s[8], sh_ss[8], sh_m[8];
    #pragma unroll
    for (int o = 16; o; o >>= 1) {
        s  += __shfl_down_sync(0xFFFFFFFFu, s, o);
        ss += __shfl_down_sync(0xFFFFFFFFu, ss, o);
    }
    if ((tid & 31) == 0) { sh_s[tid >> 5] = s; sh_ss[tid >> 5] = ss; }
    __syncthreads();
    float s_tot = 0.f, ss_tot = 0.f;
    #pragma unroll
    for (int i = 0; i < 8; ++i) { s_tot += sh_s[i]; ss_tot += sh_ss[i]; }

    float mean = s_tot * (1.0f / K_DIM);
    float var  = fmaxf(ss_tot * (1.0f / K_DIM) - mean * mean, 0.0f);
    float rstd = rsqrtf(var + 1e-5f);

    float mx = 0.f;
    #pragma unroll
    for (int i = 0; i < 8; ++i) {
        v[i] = (v[i] - mean) * rstd;
        mx = fmaxf(mx, fabsf(v[i]));
    }
    #pragma unroll
    for (int o = 16; o; o >>= 1) mx = fmaxf(mx, __shfl_down_sync(0xFFFFFFFFu, mx, o));
    if ((tid & 31) == 0) sh_m[tid >> 5] = mx;
    __syncthreads();
    float eta = 1e-5f;
    #pragma unroll
    for (int i = 0; i < 8; ++i) eta = fmaxf(eta, sh_m[i]);

    float q = 127.0f / eta;
    float b[8];
    #pragma unroll
    for (int i = 0; i < 8; ++i)
        b[i] = rintf(fminf(fmaxf(v[i] * q, -128.f), 127.f));

    __nv_bfloat162 q0 = __floats2bfloat162_rn(b[0], b[1]);
    __nv_bfloat162 q1 = __floats2bfloat162_rn(b[2], b[3]);
    __nv_bfloat162 q2 = __floats2bfloat162_rn(b[4], b[5]);
    __nv_bfloat162 q3 = __floats2bfloat162_rn(b[6], b[7]);
    uint2* xq = (uint2*)(g_xb + (size_t)row * K_DIM);
    xq[tid]       = make_uint2(*(uint32_t*)&q0, *(uint32_t*)&q1);
    xq[tid + 256] = make_uint2(*(uint32_t*)&q2, *(uint32_t*)&q3);

    if (tid == 0) g_scale[row] = g_gamma * eta * (1.0f / 127.0f);
}

// ======================= bf16 tensor-core GEMM =======================
// 256 threads = 8 warps in 2(m) x 4(n); warp tile 64x64; fragment double-buffer.
__global__ void __launch_bounds__(256, 1) gemm_hmma(float* __restrict__ out) {
    extern __shared__ char smem[];
    uint32_t sb = (smem_u32(smem) + 1023u) & ~1023u;

    const int tid  = threadIdx.x;
    const int wid  = tid >> 5;
    const int lane = tid & 31;
    const int wm   = wid >> 2;        // 0..1 (64 rows each)
    const int wn   = wid & 3;         // 0..3 (64 cols each)
    const int bx   = blockIdx.x;
    const int by   = blockIdx.y;

    const char* asrc0 = (const char*)(g_xb + (size_t)(by * BM) * K_DIM);
    const char* bsrc0 = (const char*)(g_wb + (size_t)(bx * BN) * K_DIM);

    const int lrow = lane & 15;
    const int lhi  = (lane & 16);

    // per-warp per-fragment SMEM row bases (offset within stage, pre-swizzle row part)
    // addr = base + SW128(row*128 + ks*32 + lhi); row fixed per fragment.
    float acc[4][8][4];
    #pragma unroll
    for (int mf = 0; mf < 4; ++mf)
        #pragma unroll
        for (int nf = 0; nf < 8; ++nf)
            #pragma unroll
            for (int r = 0; r < 4; ++r) acc[mf][nf][r] = 0.f;

    // ---- stage loader: 3072 x 16B, 12 per thread ----
    auto load_stage = [&](int s, int chunk) {
        uint32_t abase = sb + s * STAGE_BYTES;
        uint32_t bbase = abase + A_BYTES;
        const char* asrc = asrc0 + chunk * (BK * 2);
        const char* bsrc = bsrc0 + chunk * (BK * 2);
        #pragma unroll
        for (int j = 0; j < 12; ++j) {
            int t = tid + j * 256;
            if (t < 1024) {
                int row = t >> 3, seg = t & 7;
                cp16(abase + SW128(row * 128 + seg * 16),
                     asrc + (size_t)row * (K_DIM * 2) + seg * 16);
            } else {
                int u = t - 1024;
                int row = u >> 3, seg = u & 7;
                cp16(bbase + SW128(row * 128 + seg * 16),
                     bsrc + (size_t)row * (K_DIM * 2) + seg * 16);
            }
        }
    };

    #pragma unroll
    for (int p = 0; p < STAGES - 1; ++p) {
        load_stage(p, p);
        CP_COMMIT();
    }

    uint32_t af[2][4][4], bf[2][4][4];

    #pragma unroll 1
    for (int i = 0; i < CHUNKS; ++i) {
        CP_WAIT(STAGES - 2);
        __syncthreads();

        if (i + STAGES - 1 < CHUNKS)
            load_stage((i + STAGES - 1) % STAGES, i + STAGES - 1);
        CP_COMMIT();

        uint32_t abase = sb + (i % STAGES) * STAGE_BYTES;
        uint32_t bbase = abase + A_BYTES;

        // prime ks=0 fragments
        #pragma unroll
        for (int mf = 0; mf < 4; ++mf)
            LDSM4(af[0][mf], abase + SW128((wm * 64 + mf * 16 + lrow) * 128 + lhi));
        #pragma unroll
        for (int nf = 0; nf < 4; ++nf)
            LDSM4(bf[0][nf], bbase + SW128((wn * 64 + nf * 16 + lrow) * 128 + lhi));

        #pragma unroll
        for (int ks = 0; ks < 4; ++ks) {
            int cur = ks & 1, nxt = cur ^ 1;
            if (ks < 3) {
                #pragma unroll
                for (int mf = 0; mf < 4; ++mf)
                    LDSM4(af[nxt][mf],
                          abase + SW128((wm * 64 + mf * 16 + lrow) * 128 + (ks + 1) * 32 + lhi));
                #pragma unroll
                for (int nf = 0; nf < 4; ++nf)
                    LDSM4(bf[nxt][nf],
                          bbase + SW128((wn * 64 + nf * 16 + lrow) * 128 + (ks + 1) * 32 + lhi));
            }
            #pragma unroll
            for (int mf = 0; mf < 4; ++mf)
                #pragma unroll
                for (int nf = 0; nf < 4; ++nf) {
                    MMAB(acc[mf][2 * nf],     af[cur][mf], bf[cur][nf][0], bf[cur][nf][2]);
                    MMAB(acc[mf][2 * nf + 1], af[cur][mf], bf[cur][nf][1], bf[cur][nf][3]);
                }
        }
    }

    // ---- epilogue: scale by g_scale[m], write float2 ----
    const int row0 = by * BM + wm * 64;
    const int col0 = bx * BN + wn * 64;
    const int rq = lane >> 2;
    const int cq = (lane & 3) * 2;
    #pragma unroll
    for (int mf = 0; mf < 4; ++mf) {
        int r = row0 + mf * 16 + rq;
        float s0 = g_scale[r];
        float s1 = g_scale[r + 8];
        float* p0 = out + (size_t)r * N_OUT + col0 + cq;
        float* p1 = out + (size_t)(r + 8) * N_OUT + col0 + cq;
        #pragma unroll
        for (int nf = 0; nf < 8; ++nf) {
            float2 o0 = make_float2(acc[mf][nf][0] * s0, acc[mf][nf][1] * s0);
            float2 o1 = make_float2(acc[mf][nf][2] * s1, acc[mf][nf][3] * s1);
            *(float2*)(p0 + nf * 8) = o0;
            *(float2*)(p1 + nf * 8) = o1;
        }
    }
}

// ======================= launch =======================
extern "C" void kernel_launch(void* const* d_in, const int* in_sizes, int n_in,
                              void* d_out, int out_size) {
    const float* x = (const float*)d_in[0];
    const float* w = (const float*)d_in[1];
    float* out = (float*)d_out;

    cudaFuncSetAttribute(gemm_hmma, cudaFuncAttributeMaxDynamicSharedMemorySize, SMEM_TOTAL);

    absw_partial<<<2048, 256>>>(w);
    absw_final<<<1, 1024>>>();
    quant_w<<<4096, 256>>>(w);
    ln_quant_x<<<M_TOK, 256>>>(x);
    gemm_hmma<<<dim3(N_OUT / BN, M_TOK / BM), 256, SMEM_TOTAL>>>(out);
}

// round 7
// speedup vs baseline: 1.0477x; 1.0477x over previous
#include <cuda_runtime.h>
#include <cuda_bf16.h>
#include <cstdint>

// Shapes: x (4,2048,2048) -> M=8192, K=2048; weight (8192,2048) -> N=8192.
#define M_TOK 8192
#define K_DIM 2048
#define N_OUT 8192
#define W_ELEMS (N_OUT * K_DIM)
#define X_ELEMS (M_TOK * K_DIM)

// GEMM tiling (bf16: BK=64 elems = 128 bytes per SMEM row)
#define BM 128
#define BN 256
#define BK 64
#define CHUNKS (K_DIM / BK)          // 32
#define STAGES 4
#define A_BYTES (BM * 128)           // 16384
#define B_BYTES (BN * 128)           // 32768
#define STAGE_BYTES (A_BYTES + B_BYTES)
#define SMEM_TOTAL (1024 + STAGES * STAGE_BYTES)   // 197632

// ---- device scratch ----
__device__ float g_gamma;
__device__ float g_partial[2048];
__device__ float g_scale[M_TOK];
__device__ __nv_bfloat16 g_xb[X_ELEMS];
__device__ __nv_bfloat16 g_wb[W_ELEMS];

// ======================= helpers =======================
__device__ __forceinline__ uint32_t smem_u32(const void* p) {
    uint32_t a;
    asm("{ .reg .u64 t; cvta.to.shared.u64 t, %1; cvt.u32.u64 %0, t; }" : "=r"(a) : "l"(p));
    return a;
}
#define SW128(o) ((o) ^ (((o) >> 3) & 0x70))

__device__ __forceinline__ void cp16(uint32_t dst, const void* src) {
    asm volatile("cp.async.cg.shared.global [%0], [%1], 16;" :: "r"(dst), "l"(src));
}
#define CP_COMMIT() asm volatile("cp.async.commit_group;" ::: "memory")
#define CP_WAIT(n)  asm volatile("cp.async.wait_group %0;" :: "n"(n) : "memory")

#define LDSM4(r, a)                                                                  \
    asm volatile("ldmatrix.sync.aligned.m8n8.x4.shared.b16 {%0,%1,%2,%3}, [%4];"     \
        : "=r"((r)[0]), "=r"((r)[1]), "=r"((r)[2]), "=r"((r)[3]) : "r"(a))

#define MMAB(d, a, b0, b1)                                                           \
    asm volatile("mma.sync.aligned.m16n8k16.row.col.f32.bf16.bf16.f32 "              \
        "{%0,%1,%2,%3}, {%4,%5,%6,%7}, {%8,%9}, {%0,%1,%2,%3};"                      \
        : "+f"((d)[0]), "+f"((d)[1]), "+f"((d)[2]), "+f"((d)[3])                     \
        : "r"((a)[0]), "r"((a)[1]), "r"((a)[2]), "r"((a)[3]), "r"(b0), "r"(b1))

// ======================= prepasses =======================
__global__ void absw_partial(const float* __restrict__ w) {
    float s = 0.f;
    const float4* w4 = (const float4*)w;
    int stride = gridDim.x * blockDim.x;
    for (int i = blockIdx.x * blockDim.x + threadIdx.x; i < W_ELEMS / 4; i += stride) {
        float4 v = w4[i];
        s += fabsf(v.x) + fabsf(v.y) + fabsf(v.z) + fabsf(v.w);
    }
    __shared__ float sh[8];
    #pragma unroll
    for (int o = 16; o; o >>= 1) s += __shfl_down_sync(0xFFFFFFFFu, s, o);
    if ((threadIdx.x & 31) == 0) sh[threadIdx.x >> 5] = s;
    __syncthreads();
    if (threadIdx.x == 0) {
        float t = 0.f;
        #pragma unroll
        for (int i = 0; i < 8; ++i) t += sh[i];
        g_partial[blockIdx.x] = t;
    }
}

__global__ void absw_final() {
    float s = 0.f;
    for (int i = threadIdx.x; i < 2048; i += 1024) s += g_partial[i];
    __shared__ float sh[32];
    #pragma unroll
    for (int o = 16; o; o >>= 1) s += __shfl_down_sync(0xFFFFFFFFu, s, o);
    if ((threadIdx.x & 31) == 0) sh[threadIdx.x >> 5] = s;
    __syncthreads();
    if (threadIdx.x == 0) {
        float t = 0.f;
        #pragma unroll
        for (int i = 0; i < 32; ++i) t += sh[i];
        g_gamma = fmaxf(t / (float)W_ELEMS, 1e-5f);
    }
}

__global__ void quant_w(const float* __restrict__ w) {
    float inv_g = 1.0f / g_gamma;
    const float4* w4 = (const float4*)w;
    uint2* out = (uint2*)g_wb;
    int stride = gridDim.x * blockDim.x;
    for (int i = blockIdx.x * blockDim.x + threadIdx.x; i < W_ELEMS / 4; i += stride) {
        float4 v = w4[i];
        float b0 = rintf(fminf(fmaxf(v.x * inv_g, -1.f), 1.f));
        float b1 = rintf(fminf(fmaxf(v.y * inv_g, -1.f), 1.f));
        float b2 = rintf(fminf(fmaxf(v.z * inv_g, -1.f), 1.f));
        float b3 = rintf(fminf(fmaxf(v.w * inv_g, -1.f), 1.f));
        __nv_bfloat162 p0 = __floats2bfloat162_rn(b0, b1);
        __nv_bfloat162 p1 = __floats2bfloat162_rn(b2, b3);
        out[i] = make_uint2(*(uint32_t*)&p0, *(uint32_t*)&p1);
    }
}

__global__ void ln_quant_x(const float* __restrict__ x) {
    int row = blockIdx.x;
    const float4* xr = (const float4*)(x + (size_t)row * K_DIM);
    int tid = threadIdx.x;

    float4 p0 = xr[tid];
    float4 p1 = xr[tid + 256];
    float v[8] = {p0.x, p0.y, p0.z, p0.w, p1.x, p1.y, p1.z, p1.w};

    float s = 0.f, ss = 0.f;
    #pragma unroll
    for (int i = 0; i < 8; ++i) { s += v[i]; ss += v[i] * v[i]; }

    __shared__ float sh_s[8], sh_ss[8], sh_m[8];
    #pragma unroll
    for (int o = 16; o; o >>= 1) {
        s  += __shfl_down_sync(0xFFFFFFFFu, s, o);
        ss += __shfl_down_sync(0xFFFFFFFFu, ss, o);
    }
    if ((tid & 31) == 0) { sh_s[tid >> 5] = s; sh_ss[tid >> 5] = ss; }
    __syncthreads();
    float s_tot = 0.f, ss_tot = 0.f;
    #pragma unroll
    for (int i = 0; i < 8; ++i) { s_tot += sh_s[i]; ss_tot += sh_ss[i]; }

    float mean = s_tot * (1.0f / K_DIM);
    float var  = fmaxf(ss_tot * (1.0f / K_DIM) - mean * mean, 0.0f);
    float rstd = rsqrtf(var + 1e-5f);

    float mx = 0.f;
    #pragma unroll
    for (int i = 0; i < 8; ++i) {
        v[i] = (v[i] - mean) * rstd;
        mx = fmaxf(mx, fabsf(v[i]));
    }
    #pragma unroll
    for (int o = 16; o; o >>= 1) mx = fmaxf(mx, __shfl_down_sync(0xFFFFFFFFu, mx, o));
    if ((tid & 31) == 0) sh_m[tid >> 5] = mx;
    __syncthreads();
    float eta = 1e-5f;
    #pragma unroll
    for (int i = 0; i < 8; ++i) eta = fmaxf(eta, sh_m[i]);

    float q = 127.0f / eta;
    float b[8];
    #pragma unroll
    for (int i = 0; i < 8; ++i)
        b[i] = rintf(fminf(fmaxf(v[i] * q, -128.f), 127.f));

    __nv_bfloat162 q0 = __floats2bfloat162_rn(b[0], b[1]);
    __nv_bfloat162 q1 = __floats2bfloat162_rn(b[2], b[3]);
    __nv_bfloat162 q2 = __floats2bfloat162_rn(b[4], b[5]);
    __nv_bfloat162 q3 = __floats2bfloat162_rn(b[6], b[7]);
    uint2* xq = (uint2*)(g_xb + (size_t)row * K_DIM);
    xq[tid]       = make_uint2(*(uint32_t*)&q0, *(uint32_t*)&q1);
    xq[tid + 256] = make_uint2(*(uint32_t*)&q2, *(uint32_t*)&q3);

    if (tid == 0) g_scale[row] = g_gamma * eta * (1.0f / 127.0f);
}

// ======================= bf16 tensor-core GEMM =======================
// 512 threads = 16 warps in 4(m) x 4(n); warp tile 32x64; fragment double-buffer.
__global__ void __launch_bounds__(512, 1) gemm_hmma(float* __restrict__ out) {
    extern __shared__ char smem[];
    uint32_t sb = (smem_u32(smem) + 1023u) & ~1023u;

    const int tid  = threadIdx.x;
    const int wid  = tid >> 5;
    const int lane = tid & 31;
    const int wm   = wid >> 2;        // 0..3 (32 rows each)
    const int wn   = wid & 3;         // 0..3 (64 cols each)
    const int bx   = blockIdx.x;
    const int by   = blockIdx.y;

    const char* asrc0 = (const char*)(g_xb + (size_t)(by * BM) * K_DIM);
    const char* bsrc0 = (const char*)(g_wb + (size_t)(bx * BN) * K_DIM);

    const int lrow = lane & 15;
    const int lhi  = (lane & 16);

    float acc[2][8][4];
    #pragma unroll
    for (int mf = 0; mf < 2; ++mf)
        #pragma unroll
        for (int nf = 0; nf < 8; ++nf)
            #pragma unroll
            for (int r = 0; r < 4; ++r) acc[mf][nf][r] = 0.f;

    // ---- stage loader: 3072 x 16B, 6 per thread ----
    auto load_stage = [&](int s, int chunk) {
        uint32_t abase = sb + s * STAGE_BYTES;
        uint32_t bbase = abase + A_BYTES;
        const char* asrc = asrc0 + chunk * (BK * 2);
        const char* bsrc = bsrc0 + chunk * (BK * 2);
        #pragma unroll
        for (int j = 0; j < 6; ++j) {
            int t = tid + j * 512;
            if (t < 1024) {
                int row = t >> 3, seg = t & 7;
                cp16(abase + SW128(row * 128 + seg * 16),
                     asrc + (size_t)row * (K_DIM * 2) + seg * 16);
            } else {
                int u = t - 1024;
                int row = u >> 3, seg = u & 7;
                cp16(bbase + SW128(row * 128 + seg * 16),
                     bsrc + (size_t)row * (K_DIM * 2) + seg * 16);
            }
        }
    };

    #pragma unroll
    for (int p = 0; p < STAGES - 1; ++p) {
        load_stage(p, p);
        CP_COMMIT();
    }

    uint32_t af[2][2][4], bf[2][4][4];

    #pragma unroll 1
    for (int i = 0; i < CHUNKS; ++i) {
        CP_WAIT(STAGES - 2);
        __syncthreads();

        if (i + STAGES - 1 < CHUNKS)
            load_stage((i + STAGES - 1) % STAGES, i + STAGES - 1);
        CP_COMMIT();

        uint32_t abase = sb + (i % STAGES) * STAGE_BYTES;
        uint32_t bbase = abase + A_BYTES;

        // prime ks=0 fragments
        #pragma unroll
        for (int mf = 0; mf < 2; ++mf)
            LDSM4(af[0][mf], abase + SW128((wm * 32 + mf * 16 + lrow) * 128 + lhi));
        #pragma unroll
        for (int nf = 0; nf < 4; ++nf)
            LDSM4(bf[0][nf], bbase + SW128((wn * 64 + nf * 16 + lrow) * 128 + lhi));

        #pragma unroll
        for (int ks = 0; ks < 4; ++ks) {
            int cur = ks & 1, nxt = cur ^ 1;
            if (ks < 3) {
                #pragma unroll
                for (int mf = 0; mf < 2; ++mf)
                    LDSM4(af[nxt][mf],
                          abase + SW128((wm * 32 + mf * 16 + lrow) * 128 + (ks + 1) * 32 + lhi));
                #pragma unroll
                for (int nf = 0; nf < 4; ++nf)
                    LDSM4(bf[nxt][nf],
                          bbase + SW128((wn * 64 + nf * 16 + lrow) * 128 + (ks + 1) * 32 + lhi));
            }
            #pragma unroll
            for (int mf = 0; mf < 2; ++mf)
                #pragma unroll
                for (int nf = 0; nf < 4; ++nf) {
                    MMAB(acc[mf][2 * nf],     af[cur][mf], bf[cur][nf][0], bf[cur][nf][2]);
                    MMAB(acc[mf][2 * nf + 1], af[cur][mf], bf[cur][nf][1], bf[cur][nf][3]);
                }
        }
    }

    // ---- epilogue: scale by g_scale[m], write float2 ----
    const int row0 = by * BM + wm * 32;
    const int col0 = bx * BN + wn * 64;
    const int rq = lane >> 2;
    const int cq = (lane & 3) * 2;
    #pragma unroll
    for (int mf = 0; mf < 2; ++mf) {
        int r = row0 + mf * 16 + rq;
        float s0 = g_scale[r];
        float s1 = g_scale[r + 8];
        float* p0 = out + (size_t)r * N_OUT + col0 + cq;
        float* p1 = out + (size_t)(r + 8) * N_OUT + col0 + cq;
        #pragma unroll
        for (int nf = 0; nf < 8; ++nf) {
            float2 o0 = make_float2(acc[mf][nf][0] * s0, acc[mf][nf][1] * s0);
            float2 o1 = make_float2(acc[mf][nf][2] * s1, acc[mf][nf][3] * s1);
            *(float2*)(p0 + nf * 8) = o0;
            *(float2*)(p1 + nf * 8) = o1;
        }
    }
}

// ======================= launch =======================
extern "C" void kernel_launch(void* const* d_in, const int* in_sizes, int n_in,
                              void* d_out, int out_size) {
    const float* x = (const float*)d_in[0];
    const float* w = (const float*)d_in[1];
    float* out = (float*)d_out;

    cudaFuncSetAttribute(gemm_hmma, cudaFuncAttributeMaxDynamicSharedMemorySize, SMEM_TOTAL);

    absw_partial<<<2048, 256>>>(w);
    absw_final<<<1, 1024>>>();
    quant_w<<<4096, 256>>>(w);
    ln_quant_x<<<M_TOK, 256>>>(x);
    gemm_hmma<<<dim3(N_OUT / BN, M_TOK / BM), 512, SMEM_TOTAL>>>(out);
}

// round 8
// speedup vs baseline: 1.0709x; 1.0222x over previous
#include <cuda_runtime.h>
#include <cuda_bf16.h>
#include <cstdint>

// Shapes: x (4,2048,2048) -> M=8192, K=2048; weight (8192,2048) -> N=8192.
#define M_TOK 8192
#define K_DIM 2048
#define N_OUT 8192
#define W_ELEMS (N_OUT * K_DIM)
#define X_ELEMS (M_TOK * K_DIM)

// GEMM tiling (bf16: BK=64 elems = 128 bytes per SMEM row)
#define BM 128
#define BN 256
#define BK 64
#define CHUNKS (K_DIM / BK)          // 32 (16 pairs)
#define STAGES 4
#define A_BYTES (BM * 128)           // 16384
#define B_BYTES (BN * 128)           // 32768
#define STAGE_BYTES (A_BYTES + B_BYTES)
#define SMEM_TOTAL (1024 + STAGES * STAGE_BYTES)   // 197632

// ---- device scratch ----
__device__ float g_gamma;
__device__ float g_partial[2048];
__device__ float g_scale[M_TOK];
__device__ __nv_bfloat16 g_xb[X_ELEMS];
__device__ __nv_bfloat16 g_wb[W_ELEMS];

// ======================= helpers =======================
__device__ __forceinline__ uint32_t smem_u32(const void* p) {
    uint32_t a;
    asm("{ .reg .u64 t; cvta.to.shared.u64 t, %1; cvt.u32.u64 %0, t; }" : "=r"(a) : "l"(p));
    return a;
}
#define SW128(o) ((o) ^ (((o) >> 3) & 0x70))

__device__ __forceinline__ void cp16(uint32_t dst, const void* src) {
    asm volatile("cp.async.cg.shared.global [%0], [%1], 16;" :: "r"(dst), "l"(src));
}
#define CP_COMMIT() asm volatile("cp.async.commit_group;" ::: "memory")
#define CP_WAIT(n)  asm volatile("cp.async.wait_group %0;" :: "n"(n) : "memory")

#define LDSM4(r, a)                                                                  \
    asm volatile("ldmatrix.sync.aligned.m8n8.x4.shared.b16 {%0,%1,%2,%3}, [%4];"     \
        : "=r"((r)[0]), "=r"((r)[1]), "=r"((r)[2]), "=r"((r)[3]) : "r"(a))

#define MMAB(d, a, b0, b1)                                                           \
    asm volatile("mma.sync.aligned.m16n8k16.row.col.f32.bf16.bf16.f32 "              \
        "{%0,%1,%2,%3}, {%4,%5,%6,%7}, {%8,%9}, {%0,%1,%2,%3};"                      \
        : "+f"((d)[0]), "+f"((d)[1]), "+f"((d)[2]), "+f"((d)[3])                     \
        : "r"((a)[0]), "r"((a)[1]), "r"((a)[2]), "r"((a)[3]), "r"(b0), "r"(b1))

// ======================= prepasses =======================
__global__ void absw_partial(const float* __restrict__ w) {
    float s = 0.f;
    const float4* w4 = (const float4*)w;
    int stride = gridDim.x * blockDim.x;
    for (int i = blockIdx.x * blockDim.x + threadIdx.x; i < W_ELEMS / 4; i += stride) {
        float4 v = w4[i];
        s += fabsf(v.x) + fabsf(v.y) + fabsf(v.z) + fabsf(v.w);
    }
    __shared__ float sh[8];
    #pragma unroll
    for (int o = 16; o; o >>= 1) s += __shfl_down_sync(0xFFFFFFFFu, s, o);
    if ((threadIdx.x & 31) == 0) sh[threadIdx.x >> 5] = s;
    __syncthreads();
    if (threadIdx.x == 0) {
        float t = 0.f;
        #pragma unroll
        for (int i = 0; i < 8; ++i) t += sh[i];
        g_partial[blockIdx.x] = t;
    }
}

__global__ void absw_final() {
    float s = 0.f;
    for (int i = threadIdx.x; i < 2048; i += 1024) s += g_partial[i];
    __shared__ float sh[32];
    #pragma unroll
    for (int o = 16; o; o >>= 1) s += __shfl_down_sync(0xFFFFFFFFu, s, o);
    if ((threadIdx.x & 31) == 0) sh[threadIdx.x >> 5] = s;
    __syncthreads();
    if (threadIdx.x == 0) {
        float t = 0.f;
        #pragma unroll
        for (int i = 0; i < 32; ++i) t += sh[i];
        g_gamma = fmaxf(t / (float)W_ELEMS, 1e-5f);
    }
}

__global__ void quant_w(const float* __restrict__ w) {
    float inv_g = 1.0f / g_gamma;
    const float4* w4 = (const float4*)w;
    uint2* out = (uint2*)g_wb;
    int stride = gridDim.x * blockDim.x;
    for (int i = blockIdx.x * blockDim.x + threadIdx.x; i < W_ELEMS / 4; i += stride) {
        float4 v = w4[i];
        float b0 = rintf(fminf(fmaxf(v.x * inv_g, -1.f), 1.f));
        float b1 = rintf(fminf(fmaxf(v.y * inv_g, -1.f), 1.f));
        float b2 = rintf(fminf(fmaxf(v.z * inv_g, -1.f), 1.f));
        float b3 = rintf(fminf(fmaxf(v.w * inv_g, -1.f), 1.f));
        __nv_bfloat162 p0 = __floats2bfloat162_rn(b0, b1);
        __nv_bfloat162 p1 = __floats2bfloat162_rn(b2, b3);
        out[i] = make_uint2(*(uint32_t*)&p0, *(uint32_t*)&p1);
    }
}

__global__ void ln_quant_x(const float* __restrict__ x) {
    int row = blockIdx.x;
    const float4* xr = (const float4*)(x + (size_t)row * K_DIM);
    int tid = threadIdx.x;

    float4 p0 = xr[tid];
    float4 p1 = xr[tid + 256];
    float v[8] = {p0.x, p0.y, p0.z, p0.w, p1.x, p1.y, p1.z, p1.w};

    float s = 0.f, ss = 0.f;
    #pragma unroll
    for (int i = 0; i < 8; ++i) { s += v[i]; ss += v[i] * v[i]; }

    __shared__ float sh_s[8], sh_ss[8], sh_m[8];
    #pragma unroll
    for (int o = 16; o; o >>= 1) {
        s  += __shfl_down_sync(0xFFFFFFFFu, s, o);
        ss += __shfl_down_sync(0xFFFFFFFFu, ss, o);
    }
    if ((tid & 31) == 0) { sh_s[tid >> 5] = s; sh_ss[tid >> 5] = ss; }
    __syncthreads();
    float s_tot = 0.f, ss_tot = 0.f;
    #pragma unroll
    for (int i = 0; i < 8; ++i) { s_tot += sh_s[i]; ss_tot += sh_ss[i]; }

    float mean = s_tot * (1.0f / K_DIM);
    float var  = fmaxf(ss_tot * (1.0f / K_DIM) - mean * mean, 0.0f);
    float rstd = rsqrtf(var + 1e-5f);

    float mx = 0.f;
    #pragma unroll
    for (int i = 0; i < 8; ++i) {
        v[i] = (v[i] - mean) * rstd;
        mx = fmaxf(mx, fabsf(v[i]));
    }
    #pragma unroll
    for (int o = 16; o; o >>= 1) mx = fmaxf(mx, __shfl_down_sync(0xFFFFFFFFu, mx, o));
    if ((tid & 31) == 0) sh_m[tid >> 5] = mx;
    __syncthreads();
    float eta = 1e-5f;
    #pragma unroll
    for (int i = 0; i < 8; ++i) eta = fmaxf(eta, sh_m[i]);

    float q = 127.0f / eta;
    float b[8];
    #pragma unroll
    for (int i = 0; i < 8; ++i)
        b[i] = rintf(fminf(fmaxf(v[i] * q, -128.f), 127.f));

    __nv_bfloat162 q0 = __floats2bfloat162_rn(b[0], b[1]);
    __nv_bfloat162 q1 = __floats2bfloat162_rn(b[2], b[3]);
    __nv_bfloat162 q2 = __floats2bfloat162_rn(b[4], b[5]);
    __nv_bfloat162 q3 = __floats2bfloat162_rn(b[6], b[7]);
    uint2* xq = (uint2*)(g_xb + (size_t)row * K_DIM);
    xq[tid]       = make_uint2(*(uint32_t*)&q0, *(uint32_t*)&q1);
    xq[tid + 256] = make_uint2(*(uint32_t*)&q2, *(uint32_t*)&q3);

    if (tid == 0) g_scale[row] = g_gamma * eta * (1.0f / 127.0f);
}

// ======================= bf16 tensor-core GEMM =======================
// 512 threads = 16 warps in 4(m) x 4(n); warp tile 32x64.
// Pair-unrolled mainloop: one barrier per 2 chunks; fragment double-buffer
// carried across the chunk boundary (8 k16 steps per pair).
__global__ void __launch_bounds__(512, 1) gemm_hmma(float* __restrict__ out) {
    extern __shared__ char smem[];
    uint32_t sb = (smem_u32(smem) + 1023u) & ~1023u;

    const int tid  = threadIdx.x;
    const int lane = tid & 31;
    const int wid  = tid >> 5;
    const int wm   = wid >> 2;        // 0..3 (32 rows each)
    const int wn   = wid & 3;         // 0..3 (64 cols each)
    const int bx   = blockIdx.x;
    const int by   = blockIdx.y;

    const char* asrc0 = (const char*)(g_xb + (size_t)(by * BM) * K_DIM);
    const char* bsrc0 = (const char*)(g_wb + (size_t)(bx * BN) * K_DIM);

    const int lrow = lane & 15;
    const int lhi  = (lane & 16);

    float acc[2][8][4];
    #pragma unroll
    for (int mf = 0; mf < 2; ++mf)
        #pragma unroll
        for (int nf = 0; nf < 8; ++nf)
            #pragma unroll
            for (int r = 0; r < 4; ++r) acc[mf][nf][r] = 0.f;

    // ---- stage loader: 3072 x 16B, 6 per thread ----
    auto load_stage = [&](int s, int chunk) {
        uint32_t abase = sb + s * STAGE_BYTES;
        uint32_t bbase = abase + A_BYTES;
        const char* asrc = asrc0 + chunk * (BK * 2);
        const char* bsrc = bsrc0 + chunk * (BK * 2);
        #pragma unroll
        for (int j = 0; j < 6; ++j) {
            int t = tid + j * 512;
            if (t < 1024) {
                int row = t >> 3, seg = t & 7;
                cp16(abase + SW128(row * 128 + seg * 16),
                     asrc + (size_t)row * (K_DIM * 2) + seg * 16);
            } else {
                int u = t - 1024;
                int row = u >> 3, seg = u & 7;
                cp16(bbase + SW128(row * 128 + seg * 16),
                     bsrc + (size_t)row * (K_DIM * 2) + seg * 16);
            }
        }
    };

    // prologue: chunks 0,1 -> stages 0,1
    load_stage(0, 0);
    CP_COMMIT();
    load_stage(1, 1);
    CP_COMMIT();

    uint32_t af[2][2][4], bf[2][4][4];

    // per-warp pre-swizzle row offsets (constant parts)
    const int arow0 = wm * 32 + lrow;          // + mf*16
    const int brow0 = wn * 64 + lrow;          // + nf*16

    #pragma unroll 1
    for (int i = 0; i < CHUNKS; i += 2) {
        // wait until the pair's stages (i, i+1) are resident
        CP_WAIT(0);
        __syncthreads();    // also protects stages (i+2)%4,(i+3)%4 against WAR

        if (i + 2 < CHUNKS) {
            load_stage((i + 2) % STAGES, i + 2);
            CP_COMMIT();
            load_stage((i + 3) % STAGES, i + 3);
            CP_COMMIT();
        }

        const uint32_t ab0 = sb + (i % STAGES) * STAGE_BYTES;
        const uint32_t ab1 = sb + ((i + 1) % STAGES) * STAGE_BYTES;

        // prime ks=0 fragments from stage of chunk i
        #pragma unroll
        for (int mf = 0; mf < 2; ++mf)
            LDSM4(af[0][mf], ab0 + SW128((arow0 + mf * 16) * 128 + lhi));
        #pragma unroll
        for (int nf = 0; nf < 4; ++nf)
            LDSM4(bf[0][nf], ab0 + A_BYTES + SW128((brow0 + nf * 16) * 128 + lhi));

        // 8 k16 steps across the pair; ks>=4 reads stage of chunk i+1
        #pragma unroll
        for (int ks = 0; ks < 8; ++ks) {
            int cur = ks & 1, nxt = cur ^ 1;
            if (ks < 7) {
                int kn = ks + 1;
                uint32_t base = (kn < 4) ? ab0 : ab1;
                int ko = (kn & 3) * 32;
                #pragma unroll
                for (int mf = 0; mf < 2; ++mf)
                    LDSM4(af[nxt][mf], base + SW128((arow0 + mf * 16) * 128 + ko + lhi));
                #pragma unroll
                for (int nf = 0; nf < 4; ++nf)
                    LDSM4(bf[nxt][nf], base + A_BYTES + SW128((brow0 + nf * 16) * 128 + ko + lhi));
            }
            #pragma unroll
            for (int mf = 0; mf < 2; ++mf)
                #pragma unroll
                for (int nf = 0; nf < 4; ++nf) {
                    MMAB(acc[mf][2 * nf],     af[cur][mf], bf[cur][nf][0], bf[cur][nf][2]);
                    MMAB(acc[mf][2 * nf + 1], af[cur][mf], bf[cur][nf][1], bf[cur][nf][3]);
                }
        }
    }

    // ---- epilogue: scale by g_scale[m], write float2 ----
    const int row0 = by * BM + wm * 32;
    const int col0 = bx * BN + wn * 64;
    const int rq = lane >> 2;
    const int cq = (lane & 3) * 2;
    #pragma unroll
    for (int mf = 0; mf < 2; ++mf) {
        int r = row0 + mf * 16 + rq;
        float s0 = g_scale[r];
        float s1 = g_scale[r + 8];
        float* p0 = out + (size_t)r * N_OUT + col0 + cq;
        float* p1 = out + (size_t)(r + 8) * N_OUT + col0 + cq;
        #pragma unroll
        for (int nf = 0; nf < 8; ++nf) {
            float2 o0 = make_float2(acc[mf][nf][0] * s0, acc[mf][nf][1] * s0);
            float2 o1 = make_float2(acc[mf][nf][2] * s1, acc[mf][nf][3] * s1);
            *(float2*)(p0 + nf * 8) = o0;
            *(float2*)(p1 + nf * 8) = o1;
        }
    }
}

// ======================= launch =======================
extern "C" void kernel_launch(void* const* d_in, const int* in_sizes, int n_in,
                              void* d_out, int out_size) {
    const float* x = (const float*)d_in[0];
    const float* w = (const float*)d_in[1];
    float* out = (float*)d_out;

    cudaFuncSetAttribute(gemm_hmma, cudaFuncAttributeMaxDynamicSharedMemorySize, SMEM_TOTAL);

    absw_partial<<<2048, 256>>>(w);
    absw_final<<<1, 1024>>>();
    quant_w<<<4096, 256>>>(w);
    ln_quant_x<<<M_TOK, 256>>>(x);
    gemm_hmma<<<dim3(N_OUT / BN, M_TOK / BM), 512, SMEM_TOTAL>>>(out);
}

// round 9
// speedup vs baseline: 1.0915x; 1.0192x over previous
#include <cuda_runtime.h>
#include <cuda_bf16.h>
#include <cstdint>

// Shapes: x (4,2048,2048) -> M=8192, K=2048; weight (8192,2048) -> N=8192.
#define M_TOK 8192
#define K_DIM 2048
#define N_OUT 8192
#define W_ELEMS (N_OUT * K_DIM)
#define X_ELEMS (M_TOK * K_DIM)

// GEMM tiling (bf16: BK=64 elems = 128 bytes per SMEM row)
#define BM 128
#define BN 128
#define BK 64
#define CHUNKS (K_DIM / BK)          // 32
#define STAGES 3
#define A_BYTES (BM * 128)           // 16384
#define B_BYTES (BN * 128)           // 16384
#define STAGE_BYTES (A_BYTES + B_BYTES)   // 32768
#define SMEM_TOTAL (1024 + STAGES * STAGE_BYTES)   // 99328 -> 2 CTAs/SM

// ---- device scratch ----
__device__ float g_gamma;
__device__ float g_partial[2048];
__device__ float g_scale[M_TOK];
__device__ __nv_bfloat16 g_xb[X_ELEMS];
__device__ __nv_bfloat16 g_wb[W_ELEMS];

// ======================= helpers =======================
__device__ __forceinline__ uint32_t smem_u32(const void* p) {
    uint32_t a;
    asm("{ .reg .u64 t; cvta.to.shared.u64 t, %1; cvt.u32.u64 %0, t; }" : "=r"(a) : "l"(p));
    return a;
}
#define SW128(o) ((o) ^ (((o) >> 3) & 0x70))

__device__ __forceinline__ void cp16(uint32_t dst, const void* src) {
    asm volatile("cp.async.cg.shared.global [%0], [%1], 16;" :: "r"(dst), "l"(src));
}
#define CP_COMMIT() asm volatile("cp.async.commit_group;" ::: "memory")
#define CP_WAIT(n)  asm volatile("cp.async.wait_group %0;" :: "n"(n) : "memory")

#define LDSM4(r, a)                                                                  \
    asm volatile("ldmatrix.sync.aligned.m8n8.x4.shared.b16 {%0,%1,%2,%3}, [%4];"     \
        : "=r"((r)[0]), "=r"((r)[1]), "=r"((r)[2]), "=r"((r)[3]) : "r"(a))

#define MMAB(d, a, b0, b1)                                                           \
    asm volatile("mma.sync.aligned.m16n8k16.row.col.f32.bf16.bf16.f32 "              \
        "{%0,%1,%2,%3}, {%4,%5,%6,%7}, {%8,%9}, {%0,%1,%2,%3};"                      \
        : "+f"((d)[0]), "+f"((d)[1]), "+f"((d)[2]), "+f"((d)[3])                     \
        : "r"((a)[0]), "r"((a)[1]), "r"((a)[2]), "r"((a)[3]), "r"(b0), "r"(b1))

// ======================= prepasses =======================
__global__ void absw_partial(const float* __restrict__ w) {
    float s = 0.f;
    const float4* w4 = (const float4*)w;
    int stride = gridDim.x * blockDim.x;
    for (int i = blockIdx.x * blockDim.x + threadIdx.x; i < W_ELEMS / 4; i += stride) {
        float4 v = w4[i];
        s += fabsf(v.x) + fabsf(v.y) + fabsf(v.z) + fabsf(v.w);
    }
    __shared__ float sh[8];
    #pragma unroll
    for (int o = 16; o; o >>= 1) s += __shfl_down_sync(0xFFFFFFFFu, s, o);
    if ((threadIdx.x & 31) == 0) sh[threadIdx.x >> 5] = s;
    __syncthreads();
    if (threadIdx.x == 0) {
        float t = 0.f;
        #pragma unroll
        for (int i = 0; i < 8; ++i) t += sh[i];
        g_partial[blockIdx.x] = t;
    }
}

__global__ void absw_final() {
    float s = 0.f;
    for (int i = threadIdx.x; i < 2048; i += 1024) s += g_partial[i];
    __shared__ float sh[32];
    #pragma unroll
    for (int o = 16; o; o >>= 1) s += __shfl_down_sync(0xFFFFFFFFu, s, o);
    if ((threadIdx.x & 31) == 0) sh[threadIdx.x >> 5] = s;
    __syncthreads();
    if (threadIdx.x == 0) {
        float t = 0.f;
        #pragma unroll
        for (int i = 0; i < 32; ++i) t += sh[i];
        g_gamma = fmaxf(t / (float)W_ELEMS, 1e-5f);
    }
}

__global__ void quant_w(const float* __restrict__ w) {
    float inv_g = 1.0f / g_gamma;
    const float4* w4 = (const float4*)w;
    uint2* out = (uint2*)g_wb;
    int stride = gridDim.x * blockDim.x;
    for (int i = blockIdx.x * blockDim.x + threadIdx.x; i < W_ELEMS / 4; i += stride) {
        float4 v = w4[i];
        float b0 = rintf(fminf(fmaxf(v.x * inv_g, -1.f), 1.f));
        float b1 = rintf(fminf(fmaxf(v.y * inv_g, -1.f), 1.f));
        float b2 = rintf(fminf(fmaxf(v.z * inv_g, -1.f), 1.f));
        float b3 = rintf(fminf(fmaxf(v.w * inv_g, -1.f), 1.f));
        __nv_bfloat162 p0 = __floats2bfloat162_rn(b0, b1);
        __nv_bfloat162 p1 = __floats2bfloat162_rn(b2, b3);
        out[i] = make_uint2(*(uint32_t*)&p0, *(uint32_t*)&p1);
    }
}

__global__ void ln_quant_x(const float* __restrict__ x) {
    int row = blockIdx.x;
    const float4* xr = (const float4*)(x + (size_t)row * K_DIM);
    int tid = threadIdx.x;

    float4 p0 = xr[tid];
    float4 p1 = xr[tid + 256];
    float v[8] = {p0.x, p0.y, p0.z, p0.w, p1.x, p1.y, p1.z, p1.w};

    float s = 0.f, ss = 0.f;
    #pragma unroll
    for (int i = 0; i < 8; ++i) { s += v[i]; ss += v[i] * v[i]; }

    __shared__ float sh_s[8], sh_ss[8], sh_m[8];
    #pragma unroll
    for (int o = 16; o; o >>= 1) {
        s  += __shfl_down_sync(0xFFFFFFFFu, s, o);
        ss += __shfl_down_sync(0xFFFFFFFFu, ss, o);
    }
    if ((tid & 31) == 0) { sh_s[tid >> 5] = s; sh_ss[tid >> 5] = ss; }
    __syncthreads();
    float s_tot = 0.f, ss_tot = 0.f;
    #pragma unroll
    for (int i = 0; i < 8; ++i) { s_tot += sh_s[i]; ss_tot += sh_ss[i]; }

    float mean = s_tot * (1.0f / K_DIM);
    float var  = fmaxf(ss_tot * (1.0f / K_DIM) - mean * mean, 0.0f);
    float rstd = rsqrtf(var + 1e-5f);

    float mx = 0.f;
    #pragma unroll
    for (int i = 0; i < 8; ++i) {
        v[i] = (v[i] - mean) * rstd;
        mx = fmaxf(mx, fabsf(v[i]));
    }
    #pragma unroll
    for (int o = 16; o; o >>= 1) mx = fmaxf(mx, __shfl_down_sync(0xFFFFFFFFu, mx, o));
    if ((tid & 31) == 0) sh_m[tid >> 5] = mx;
    __syncthreads();
    float eta = 1e-5f;
    #pragma unroll
    for (int i = 0; i < 8; ++i) eta = fmaxf(eta, sh_m[i]);

    float q = 127.0f / eta;
    float b[8];
    #pragma unroll
    for (int i = 0; i < 8; ++i)
        b[i] = rintf(fminf(fmaxf(v[i] * q, -128.f), 127.f));

    __nv_bfloat162 q0 = __floats2bfloat162_rn(b[0], b[1]);
    __nv_bfloat162 q1 = __floats2bfloat162_rn(b[2], b[3]);
    __nv_bfloat162 q2 = __floats2bfloat162_rn(b[4], b[5]);
    __nv_bfloat162 q3 = __floats2bfloat162_rn(b[6], b[7]);
    uint2* xq = (uint2*)(g_xb + (size_t)row * K_DIM);
    xq[tid]       = make_uint2(*(uint32_t*)&q0, *(uint32_t*)&q1);
    xq[tid + 256] = make_uint2(*(uint32_t*)&q2, *(uint32_t*)&q3);

    if (tid == 0) g_scale[row] = g_gamma * eta * (1.0f / 127.0f);
}

// ======================= bf16 tensor-core GEMM =======================
// 256 threads = 8 warps in 2(m) x 4(n); warp tile 64x32; 2 CTAs per SM.
__global__ void __launch_bounds__(256, 2) gemm_hmma(float* __restrict__ out) {
    extern __shared__ char smem[];
    uint32_t sb = (smem_u32(smem) + 1023u) & ~1023u;

    const int tid  = threadIdx.x;
    const int lane = tid & 31;
    const int wid  = tid >> 5;
    const int wm   = wid >> 2;        // 0..1 (64 rows each)
    const int wn   = wid & 3;         // 0..3 (32 cols each)
    const int bx   = blockIdx.x;
    const int by   = blockIdx.y;

    const char* asrc0 = (const char*)(g_xb + (size_t)(by * BM) * K_DIM);
    const char* bsrc0 = (const char*)(g_wb + (size_t)(bx * BN) * K_DIM);

    const int lrow = lane & 15;
    const int lhi  = (lane & 16);

    float acc[4][4][4];
    #pragma unroll
    for (int mf = 0; mf < 4; ++mf)
        #pragma unroll
        for (int nf = 0; nf < 4; ++nf)
            #pragma unroll
            for (int r = 0; r < 4; ++r) acc[mf][nf][r] = 0.f;

    // ---- stage loader: 2048 x 16B, 8 per thread ----
    auto load_stage = [&](int s, int chunk) {
        uint32_t abase = sb + s * STAGE_BYTES;
        uint32_t bbase = abase + A_BYTES;
        const char* asrc = asrc0 + chunk * (BK * 2);
        const char* bsrc = bsrc0 + chunk * (BK * 2);
        #pragma unroll
        for (int j = 0; j < 8; ++j) {
            int t = tid + j * 256;
            if (t < 1024) {
                int row = t >> 3, seg = t & 7;
                cp16(abase + SW128(row * 128 + seg * 16),
                     asrc + (size_t)row * (K_DIM * 2) + seg * 16);
            } else {
                int u = t - 1024;
                int row = u >> 3, seg = u & 7;
                cp16(bbase + SW128(row * 128 + seg * 16),
                     bsrc + (size_t)row * (K_DIM * 2) + seg * 16);
            }
        }
    };

    load_stage(0, 0);
    CP_COMMIT();
    load_stage(1, 1);
    CP_COMMIT();

    const int arow0 = wm * 64 + lrow;          // + mf*16
    const int brow0 = wn * 32 + lrow;          // + nf2*16

    #pragma unroll 1
    for (int i = 0; i < CHUNKS; ++i) {
        CP_WAIT(1);
        __syncthreads();

        if (i + 2 < CHUNKS)
            load_stage((i + 2) % STAGES, i + 2);
        CP_COMMIT();

        uint32_t abase = sb + (i % STAGES) * STAGE_BYTES;
        uint32_t bbase = abase + A_BYTES;

        #pragma unroll
        for (int ks = 0; ks < 4; ++ks) {
            uint32_t a[4][4], b[2][4];
            #pragma unroll
            for (int mf = 0; mf < 4; ++mf)
                LDSM4(a[mf], abase + SW128((arow0 + mf * 16) * 128 + ks * 32 + lhi));
            #pragma unroll
            for (int nf2 = 0; nf2 < 2; ++nf2)
                LDSM4(b[nf2], bbase + SW128((brow0 + nf2 * 16) * 128 + ks * 32 + lhi));
            #pragma unroll
            for (int mf = 0; mf < 4; ++mf)
                #pragma unroll
                for (int nf2 = 0; nf2 < 2; ++nf2) {
                    MMAB(acc[mf][2 * nf2],     a[mf], b[nf2][0], b[nf2][2]);
                    MMAB(acc[mf][2 * nf2 + 1], a[mf], b[nf2][1], b[nf2][3]);
                }
        }
    }

    // ---- epilogue: scale by g_scale[m], write float2 ----
    const int row0 = by * BM + wm * 64;
    const int col0 = bx * BN + wn * 32;
    const int rq = lane >> 2;
    const int cq = (lane & 3) * 2;
    #pragma unroll
    for (int mf = 0; mf < 4; ++mf) {
        int r = row0 + mf * 16 + rq;
        float s0 = g_scale[r];
        float s1 = g_scale[r + 8];
        float* p0 = out + (size_t)r * N_OUT + col0 + cq;
        float* p1 = out + (size_t)(r + 8) * N_OUT + col0 + cq;
        #pragma unroll
        for (int nf = 0; nf < 4; ++nf) {
            float2 o0 = make_float2(acc[mf][nf][0] * s0, acc[mf][nf][1] * s0);
            float2 o1 = make_float2(acc[mf][nf][2] * s1, acc[mf][nf][3] * s1);
            *(float2*)(p0 + nf * 8) = o0;
            *(float2*)(p1 + nf * 8) = o1;
        }
    }
}

// ======================= launch =======================
extern "C" void kernel_launch(void* const* d_in, const int* in_sizes, int n_in,
                              void* d_out, int out_size) {
    const float* x = (const float*)d_in[0];
    const float* w = (const float*)d_in[1];
    float* out = (float*)d_out;

    cudaFuncSetAttribute(gemm_hmma, cudaFuncAttributeMaxDynamicSharedMemorySize, SMEM_TOTAL);

    absw_partial<<<2048, 256>>>(w);
    absw_final<<<1, 1024>>>();
    quant_w<<<4096, 256>>>(w);
    ln_quant_x<<<M_TOK, 256>>>(x);
    gemm_hmma<<<dim3(N_OUT / BN, M_TOK / BM), 256, SMEM_TOTAL>>>(out);
}